// round 16
// baseline (speedup 1.0000x reference)
#include <cuda_runtime.h>
#include <cstdint>

#define SZ 512
#define NPLANES 256
#define NTASKS_PP 6          // per-plane: 3 full + 1 half + 2 quarter

// dynamic smem layout (bytes) — sized for max task (128 rows)
#define OFF_ROWP 0                     // float[4][128][33] row partials
#define OFF_COLP 67584                 // float[4][512]
#define OFF_PKM  75776                 // float[128]
#define OFF_PKA  76288
#define OFF_SNM  76800
#define OFF_SNA  77312
#define OFF_DAE  77824
#define OFF_BAND 78336                 // float[4][128]
#define OFF_CUTM 80384
#define OFF_CUTA 80896
#define SMEM_TOTAL 81408

// cross-block scratch (allocation-free: __device__ globals)
__device__ float g_colsum[NPLANES][NTASKS_PP][SZ];
__device__ float g_snapM[NPLANES][SZ];
__device__ float g_snapA[NPLANES][SZ];
__device__ float g_RT[NPLANES][SZ];
__device__ float g_PM[NPLANES][SZ];
__device__ float g_PA[NPLANES][SZ];
__device__ float g_DA[NPLANES][SZ];
__device__ unsigned int g_cnt[NPLANES];   // zero-init; self-reset each launch

__device__ __forceinline__ uint64_t pack2(float lo, float hi) {
    uint64_t d; asm("mov.b64 %0, {%1, %2};" : "=l"(d) : "f"(lo), "f"(hi)); return d;
}
__device__ __forceinline__ void unpack2(uint64_t d, float& lo, float& hi) {
    asm("mov.b64 {%0, %1}, %2;" : "=f"(lo), "=f"(hi) : "l"(d));
}
__device__ __forceinline__ uint64_t addf32x2(uint64_t a, uint64_t b) {
    uint64_t d; asm("add.rn.f32x2 %0, %1, %2;" : "=l"(d) : "l"(a), "l"(b)); return d;
}

// task index of the row-interval containing global row r (boundaries 0,128,256,384,448,480,512)
__device__ __forceinline__ int task_of_row(int r) {
    int j = r >> 7;
    if (j >= 3) j = (r < 448) ? 3 : (r < 480) ? 4 : 5;
    return j;
}

__global__ __launch_bounds__(512, 2)
void slab_kernel(const float* __restrict__ x, float* __restrict__ out) {
    extern __shared__ char SB[];
    float* sRowPart = (float*)(SB + OFF_ROWP);   // [(band*128+lr)*33 + lane]
    float* sColPart = (float*)(SB + OFF_COLP);   // [rowgroup*512 + col]
    float* sPkM     = (float*)(SB + OFF_PKM);
    float* sPkA     = (float*)(SB + OFF_PKA);
    float* sSnapM   = (float*)(SB + OFF_SNM);    // row-indexed (lr)
    float* sSnapA   = (float*)(SB + OFF_SNA);    // row-indexed (lr)
    float* sDA      = (float*)(SB + OFF_DAE);
    float* sBandRow = (float*)(SB + OFF_BAND);   // [band*128 + lr]
    float* sCutM    = (float*)(SB + OFF_CUTM);
    float* sCutA    = (float*)(SB + OFF_CUTA);
    // last-block combine arrays alias the (dead-by-then) sRowPart region
    float* cA1  = (float*)(SB + 0);
    float* cA2  = (float*)(SB + 2048);
    float* cCT  = (float*)(SB + 4096);
    float* cRT  = (float*)(SB + 6144);
    float* cPM  = (float*)(SB + 8192);
    float* cPA  = (float*)(SB + 10240);
    float* cDAo = (float*)(SB + 12288);
    __shared__ bool amLast;

    // ---- task decode: bids ordered full(0..767) -> half(768..1023) -> quarter(1024..1535)
    const int t = blockIdx.x;
    int p, tidx, row0, nrows;
    if (t < 768)       { p = t / 3;       tidx = t - 3 * p;  row0 = tidx * 128;          nrows = 128; }
    else if (t < 1024) { p = t - 768;     tidx = 3;          row0 = 384;                 nrows = 64;  }
    else               { int u = t - 1024; p = u >> 1;       tidx = 4 + (u & 1);         row0 = 448 + (u & 1) * 32; nrows = 32; }

    const int lg  = (nrows == 128) ? 7 : (nrows == 64) ? 6 : 5;   // log2(nrows)
    const int rpg = nrows >> 2;            // rows per rowgroup
    const int mb  = row0 >> 7;             // main-cut band (constant per task)
    const int base = row0 & 127;           // col offset of main cut within band

    const float* __restrict__ X = x + ((size_t)p * SZ + (size_t)row0) * SZ;

    const int tid  = threadIdx.x;
    const int w    = tid >> 5;
    const int lane = tid & 31;
    const int wr = w >> 2, wc = w & 3;     // 4 rowgroups x 4 col bands
    const int c0  = wc * 128;
    const int lr0 = wr * rpg;
    const bool mainRole = (wc == mb);
    const bool antiRole = (wc == 3 - mb);

    const float4* __restrict__ basep =
        reinterpret_cast<const float4*>(X + (size_t)lr0 * SZ + c0) + lane;
    const int RS4 = SZ / 4;

    uint64_t acc01 = 0ull, acc23 = 0ull;

    const int ngroups = nrows >> 5;        // 8-row groups per warp: 4/2/1
    for (int g = 0; g < ngroups; ++g) {
        const int lrg = lr0 + 8 * g;

        float4 v[8];
#pragma unroll
        for (int u = 0; u < 8; u++)
            v[u] = __ldcs(basep + (8 * g + u) * RS4);

        float sv[8];
#pragma unroll
        for (int u = 0; u < 8; u++) {
            uint64_t h = addf32x2(pack2(v[u].x, v[u].y), pack2(v[u].z, v[u].w));
            float lo, hi; unpack2(h, lo, hi);
            sv[u] = lo + hi;
        }

        // store per-lane row partials (conflict-free)
        {
            float* rp = sRowPart + (wc * 128 + lrg) * 33 + lane;
#pragma unroll
            for (int u = 0; u < 8; u++)
                rp[u * 33] = sv[u];
        }

        const int lsMg = (base + lrg) >> 2;          // (base+lrg) % 4 == 0
        const int lsAg = (127 - base - lrg) >> 2;    // (127-base-lrg) % 4 == 3

        // role-warp scalars + packed acc update
#pragma unroll
        for (int u = 0; u < 8; u++) {
            const int lr = lrg + u;
            if (mainRole) {
                const int ls = lsMg + (u >> 2);
                const int k = u & 3;                  // compile-time
                if (lane == ls) {
                    const float pkv = (k == 0) ? v[u].x
                                    : (k == 1) ? (v[u].x + v[u].y)
                                    : (k == 2) ? ((v[u].x + v[u].y) + v[u].z)
                                    : sv[u];
                    sPkM[lr] = pkv;
                    float lo, hi, sn;
                    if (k < 2) { unpack2(acc01, lo, hi); sn = (k == 0) ? lo : hi; }
                    else       { unpack2(acc23, lo, hi); sn = (k == 2) ? lo : hi; }
                    sSnapM[lr] = sn;
                }
            }
            if (antiRole) {
                const int lsA = lsAg - (u >> 2);
                const int kA = 3 - (u & 3);           // compile-time
                if (lane == lsA) {
                    const float pkv = (kA == 3) ? sv[u]
                                    : (kA == 2) ? ((v[u].x + v[u].y) + v[u].z)
                                    : (kA == 1) ? (v[u].x + v[u].y)
                                    : v[u].x;
                    sPkA[lr] = pkv;
                    const float e = (kA == 0) ? v[u].x : (kA == 1) ? v[u].y
                                  : (kA == 2) ? v[u].z : v[u].w;
                    float lo, hi, sn;
                    if (kA < 2) { unpack2(acc01, lo, hi); sn = (kA == 0) ? lo : hi; }
                    else        { unpack2(acc23, lo, hi); sn = (kA == 2) ? lo : hi; }
                    sSnapA[lr] = sn;
                    sDA[lr] = e;
                }
            }
            acc01 = addf32x2(acc01, pack2(v[u].x, v[u].y));
            acc23 = addf32x2(acc23, pack2(v[u].z, v[u].w));
        }
    }

    {
        float a0, a1, a2, a3;
        unpack2(acc01, a0, a1);
        unpack2(acc23, a2, a3);
        *reinterpret_cast<float4*>(sColPart + wr * SZ + c0 + lane * 4) = make_float4(a0, a1, a2, a3);
    }
    __syncthreads();

    // ---- phase 2a: reduce row partials from smem (no shuffles) ----
    if (tid < 4 * nrows) {
        const int band = tid >> lg;
        const int lr = tid & (nrows - 1);
        const float* rp = sRowPart + (band * 128 + lr) * 33;
        const int lsM = (base + lr) >> 2;
        const int lsA = (127 - base - lr) >> 2;
        float full = 0.f, cutM = 0.f, cutA = 0.f;
#pragma unroll
        for (int k = 0; k < 32; ++k) {
            const float vv = rp[k];
            full += vv;
            if (k < lsM) cutM += vv;
            if (k < lsA) cutA += vv;
        }
        sBandRow[band * 128 + lr] = full;
        if (band == mb)     sCutM[lr] = cutM + sPkM[lr];
        if (band == 3 - mb) sCutA[lr] = cutA + sPkA[lr];
    }
    // ---- task combine: columns ----
    {
        const int c = tid;
        const float q0 = sColPart[0 * SZ + c], q1 = sColPart[1 * SZ + c],
                    q2 = sColPart[2 * SZ + c], q3 = sColPart[3 * SZ + c];
        g_colsum[p][tidx][c] = (q0 + q1) + (q2 + q3);

        const int rgsh = lg - 2;                     // log2(rpg)
        if ((unsigned)(c - row0) < (unsigned)nrows) {        // main-diag owner
            const int lr = c - row0;
            const int rg = lr >> rgsh;
            float sn = sSnapM[lr];
            if (rg > 0) sn += q0;
            if (rg > 1) sn += q1;
            if (rg > 2) sn += q2;
            g_snapM[p][c] = sn;
        }
        const int ar = SZ - 1 - c;
        if ((unsigned)(ar - row0) < (unsigned)nrows) {       // anti-diag owner
            const int lr = ar - row0;
            const int rg = lr >> rgsh;
            float sn = sSnapA[lr];
            if (rg > 0) sn += q0;
            if (rg > 1) sn += q1;
            if (rg > 2) sn += q2;
            g_snapA[p][c] = sn;
        }
    }
    __syncthreads();

    // ---- task combine: rows ----
    if (tid < nrows) {
        const int lr = tid;
        const int gr = row0 + lr;
        const float b0 = sBandRow[0 * 128 + lr], b1 = sBandRow[1 * 128 + lr],
                    b2 = sBandRow[2 * 128 + lr], b3 = sBandRow[3 * 128 + lr];
        g_RT[p][gr] = (b0 + b1) + (b2 + b3);

        float pm = sCutM[lr];
        if (mb > 0) pm += b0;
        if (mb > 1) pm += b1;
        if (mb > 2) pm += b2;
        g_PM[p][gr] = pm;

        const int ab = 3 - mb;
        float pa = sCutA[lr];
        if (ab > 0) pa += b0;
        if (ab > 1) pa += b1;
        if (ab > 2) pa += b2;
        g_PA[p][gr] = pa;

        g_DA[p][gr] = sDA[lr];
    }

    // ---- last-task-per-plane fused combine ----
    __threadfence();
    __syncthreads();
    if (tid == 0) {
        const unsigned tt = atomicAdd(&g_cnt[p], 1u);
        amLast = (tt == NTASKS_PP - 1u);
        if (amLast) g_cnt[p] = 0;
    }
    __syncthreads();
    if (!amLast) return;

    {
        const int i = tid;
        float q[NTASKS_PP];
#pragma unroll
        for (int k = 0; k < NTASKS_PP; k++) q[k] = g_colsum[p][k][i];
        float ct = 0.f;
#pragma unroll
        for (int k = 0; k < NTASKS_PP; k++) ct += q[k];
        cCT[i] = ct;

        const int jm = task_of_row(i);
        float a1 = g_snapM[p][i];
#pragma unroll
        for (int k = 0; k < NTASKS_PP - 1; k++) if (k < jm) a1 += q[k];
        cA1[i] = a1;

        const int ja = task_of_row(SZ - 1 - i);
        float a2 = g_snapA[p][i];
#pragma unroll
        for (int k = 0; k < NTASKS_PP - 1; k++) if (k < ja) a2 += q[k];
        cA2[i] = a2;

        cRT[i] = g_RT[p][i]; cPM[i] = g_PM[p][i]; cPA[i] = g_PA[p][i]; cDAo[i] = g_DA[p][i];
    }
    __syncthreads();
    {
        const int i = tid;
        const int m = SZ - 1 - i;

        const float tl = cPM[i] + cA1[i];
        const float tr = cRT[i] - cPA[i] + cDAo[i] + cA2[m];
        const float bl = cPA[m] + cCT[i] - cA2[i] - cDAo[m];
        const float br = cRT[m] - cPM[m] + cCT[m] - cA1[m];

        const float inv = 1.0f / (float)(2 * i + 1);
        const int b  = p >> 3;
        const int ch = p & 7;
        float* __restrict__ o = out + ((size_t)(b * SZ + i)) * 32 + ch;
        o[0]  = tl * inv;
        o[8]  = tr * inv;
        o[16] = bl * inv;
        o[24] = br * inv;
    }
}

extern "C" void kernel_launch(void* const* d_in, const int* in_sizes, int n_in,
                              void* d_out, int out_size) {
    const float* x = (const float*)d_in[0];
    float* out = (float*)d_out;
    static bool attrSet = false;
    if (!attrSet) {
        cudaFuncSetAttribute(slab_kernel, cudaFuncAttributeMaxDynamicSharedMemorySize, SMEM_TOTAL);
        attrSet = true;
    }
    slab_kernel<<<NPLANES * NTASKS_PP, 512, SMEM_TOTAL>>>(x, out);
}